// round 16
// baseline (speedup 1.0000x reference)
#include <cuda_runtime.h>
#include <mma.h>
#include <cuda_fp16.h>
#include <cstdint>

using namespace nvcuda;

#define NN 10000
#define NE 320000
#define DD 128
#define HH 512

#define NX  (NN * DD)
#define NEA (NE * DD)

// ---------------- static device scratch ----------------
__device__ float  g_agg[NX];
__device__ __half g_aggh[NX];
__device__ __half g_xh[NX];
__device__ __half g_eah[NEA];
__device__ __half g_W1h[384 * 512];
__device__ __half g_W2h[512 * 128];
__device__ __half g_Wn1h[256 * 512];
__device__ __half g_Wn2h[512 * 128];
__device__ __half g_Hn[NN * HH];        // node-MLP hidden
__device__ float  g_Z1[NN * HH];        // x @ We1[0:128] + b1   (fp32, L2-resident)
__device__ float  g_Z2[NN * HH];        // x @ We1[128:256]

// ---------------- helpers ----------------
__device__ __forceinline__ uint32_t smem_u32(const void* p) {
    uint32_t a;
    asm("{ .reg .u64 t; cvta.to.shared.u64 t, %1; cvt.u32.u64 %0, t; }" : "=r"(a) : "l"(p));
    return a;
}
__device__ __forceinline__ void cpa16h(__half* s, const __half* g) {
    asm volatile("cp.async.cg.shared.global [%0], [%1], 16;"
                 :: "r"(smem_u32(s)), "l"(g) : "memory");
}
__device__ __forceinline__ void cp_commit() {
    asm volatile("cp.async.commit_group;" ::: "memory");
}
template<int N> __device__ __forceinline__ void cp_wait() {
    asm volatile("cp.async.wait_group %0;" :: "n"(N) : "memory");
}

using FragA = wmma::fragment<wmma::matrix_a, 16, 16, 16, __half, wmma::row_major>;
using FragB = wmma::fragment<wmma::matrix_b, 16, 16, 16, __half, wmma::row_major>;
using FragC = wmma::fragment<wmma::accumulator, 16, 16, 16, float>;

#define LDA_H 40
#define LDB_H 136
#define LDC   132
#define NS    3

// ---- 32x64 warp tile (z/n1/n2 kernels, 256 thr) ----
__device__ __forceinline__ void mma_chunk(const __half* __restrict__ A,
                                          const __half* __restrict__ B,
                                          FragC (&acc)[2][4], int m0, int n0)
{
    #pragma unroll
    for (int s = 0; s < 2; s++) {
        FragA af[2];
        FragB bf[4];
        #pragma unroll
        for (int i = 0; i < 2; i++)
            wmma::load_matrix_sync(af[i], A + (m0 + i * 16) * LDA_H + s * 16, LDA_H);
        #pragma unroll
        for (int j = 0; j < 4; j++)
            wmma::load_matrix_sync(bf[j], B + (s * 16) * LDB_H + n0 + j * 16, LDB_H);
        #pragma unroll
        for (int i = 0; i < 2; i++)
            #pragma unroll
            for (int j = 0; j < 4; j++)
                wmma::mma_sync(acc[i][j], af[i], bf[j], acc[i][j]);
    }
}

// ---- 32x32 warp tile (fused kernel, 512 thr); A stride passed in ----
__device__ __forceinline__ void mma_32x32(const __half* __restrict__ A, int lda,
                                          const __half* __restrict__ B,
                                          FragC (&acc)[2][2], int m0, int n0)
{
    #pragma unroll
    for (int s = 0; s < 2; s++) {
        FragA af[2];
        FragB bf[2];
        #pragma unroll
        for (int i = 0; i < 2; i++)
            wmma::load_matrix_sync(af[i], A + (m0 + i * 16) * lda + s * 16, lda);
        #pragma unroll
        for (int j = 0; j < 2; j++)
            wmma::load_matrix_sync(bf[j], B + (s * 16) * LDB_H + n0 + j * 16, LDB_H);
        #pragma unroll
        for (int i = 0; i < 2; i++)
            #pragma unroll
            for (int j = 0; j < 2; j++)
                wmma::mma_sync(acc[i][j], af[i], bf[j], acc[i][j]);
    }
}

// ---------------- smem layout: z/n1/n2 (256 thr, 2 CTAs/SM) ----------------
#define ASZB 10240
#define BSZB 8704
#define OFF_A(s) ((s) * ASZB)
#define OFF_B(s) (NS * ASZB + (s) * BSZB)
#define OFF_BIAS 67584
#define OFF_IDX  68096
#define SMEM_BYTES 69120

#define GEMM_MAIN(KC, LOADA, LOADB)                                          \
    {                                                                        \
        _Pragma("unroll")                                                    \
        for (int s = 0; s < NS - 1; s++) { LOADA(s, s); LOADB(s, s); cp_commit(); } \
        for (int kc = 0; kc < (KC); kc++) {                                  \
            if (kc < (KC) - 1) cp_wait<1>(); else cp_wait<0>();              \
            __syncthreads();                                                 \
            if (kc + NS - 1 < (KC)) {                                        \
                LOADA((kc + NS - 1) % NS, kc + NS - 1);                      \
                LOADB((kc + NS - 1) % NS, kc + NS - 1);                      \
                cp_commit();                                                 \
            }                                                                \
            int cur = kc % NS;                                               \
            mma_chunk((__half*)(smc + OFF_A(cur)), (__half*)(smc + OFF_B(cur)), \
                      acc, m0, n0);                                          \
        }                                                                    \
        __syncthreads();                                                     \
    }

#define STORE_C()                                                            \
    {                                                                        \
        _Pragma("unroll")                                                    \
        for (int i = 0; i < 2; i++)                                          \
            _Pragma("unroll")                                                \
            for (int j = 0; j < 4; j++)                                      \
                wmma::store_matrix_sync(Cs + (m0 + i * 16) * LDC + n0 + j * 16, \
                                        acc[i][j], LDC, wmma::mem_row_major); \
        __syncthreads();                                                     \
    }

// ---------------- smem layout: fused edge kernel (512 thr, 1 CTA/SM) ----------------
#define LDH 520
#define OFF_H 0
#define HBYTES (128 * LDH * 2)                    // 133120
#define OFF_PC HBYTES
#define FA_ST(s) (OFF_PC + (s) * ASZB)
#define FB_ST(s) (OFF_PC + 3 * ASZB + (s) * BSZB)
#define PC_BYTES 67584
#define FOFF_BIAS (OFF_PC + PC_BYTES)             // 200704
#define FOFF_IDX  (FOFF_BIAS + 512)               // 201216
#define FUSED_SMEM (FOFF_IDX + 1024)              // 202240

// ---------------- aux kernels ----------------
__global__ void dummy_kernel() {}

__device__ __forceinline__ void cvt4(__half* dst, const float* src) {
    float4 v = *(const float4*)src;
    __half2* d = (__half2*)dst;
    d[0] = __floats2half2_rn(v.x, v.y);
    d[1] = __floats2half2_rn(v.z, v.w);
}

__global__ void prep_kernel(const float* __restrict__ x, const float* __restrict__ ea,
                            const float* __restrict__ We1, const float* __restrict__ We2,
                            const float* __restrict__ Wn1, const float* __restrict__ Wn2)
{
    const int total4 = (NX + NEA + 196608 + 65536 + 131072 + 65536) / 4;
    for (int i = blockIdx.x * blockDim.x + threadIdx.x; i < total4; i += gridDim.x * blockDim.x) {
        int k = i * 4;
        if (k < NX)     { cvt4(g_xh + k, x + k);     continue; }
        k -= NX;
        if (k < NEA)    { cvt4(g_eah + k, ea + k);   continue; }
        k -= NEA;
        if (k < 196608) { cvt4(g_W1h + k, We1 + k);  continue; }
        k -= 196608;
        if (k < 65536)  { cvt4(g_W2h + k, We2 + k);  continue; }
        k -= 65536;
        if (k < 131072) { cvt4(g_Wn1h + k, Wn1 + k); continue; }
        k -= 131072;
        cvt4(g_Wn2h + k, Wn2 + k);
    }
}

__global__ void cvt_agg_kernel() {
    for (int i = blockIdx.x * blockDim.x + threadIdx.x; i * 4 < NX; i += gridDim.x * blockDim.x) {
        float4 v = *(const float4*)(g_agg + i * 4);
        __half2* d = (__half2*)(g_aggh + i * 4);
        d[0] = __floats2half2_rn(v.x, v.y);
        d[1] = __floats2half2_rn(v.z, v.w);
    }
}

// =====================================================================
// Z: g_Z1 = x @ We1[0:128] + b1 ; g_Z2 = x @ We1[128:256]  (fp32 out)
// grid (79, 4, 2). CTA 128x128, K=128
// =====================================================================
__global__ __launch_bounds__(256, 2)
void z_kernel(const float* __restrict__ b1)
{
    extern __shared__ char smc[];
    float* Cs = (float*)smc;
    float* bs = (float*)(smc + OFF_BIAS);

    const int tid = threadIdx.x;
    const int w = tid >> 5;
    const int m0 = (w >> 1) * 32, n0 = (w & 1) * 64;
    const int nb0 = blockIdx.x * 128;
    const int cb  = blockIdx.y;
    const int zsel = blockIdx.z;

    if (tid < 128) bs[tid] = (zsel == 0) ? b1[cb * 128 + tid] : 0.0f;
    __syncthreads();

    auto loadA = [&](int buf, int kc) {
        #pragma unroll
        for (int i = tid; i < 512; i += 256) {
            int row = i >> 2, seg = i & 3;
            int nr = min(nb0 + row, NN - 1);
            cpa16h((__half*)(smc + OFF_A(buf)) + row * LDA_H + seg * 8,
                   g_xh + (size_t)nr * DD + kc * 32 + seg * 8);
        }
    };
    auto loadB = [&](int buf, int kc) {
        #pragma unroll
        for (int i = tid; i < 512; i += 256) {
            int row = i >> 4, seg = i & 15;
            cpa16h((__half*)(smc + OFF_B(buf)) + row * LDB_H + seg * 8,
                   g_W1h + (size_t)(zsel * 128 + kc * 32 + row) * HH + cb * 128 + seg * 8);
        }
    };

    FragC acc[2][4];
    #pragma unroll
    for (int i = 0; i < 2; i++)
        #pragma unroll
        for (int j = 0; j < 4; j++) wmma::fill_fragment(acc[i][j], 0.0f);

    GEMM_MAIN(4, loadA, loadB);
    STORE_C();

    float* dst = zsel == 0 ? g_Z1 : g_Z2;
    for (int idx = tid; idx < 16384; idx += 256) {
        int r = idx >> 7, c = idx & 127;
        int n = nb0 + r;
        if (n < NN)
            dst[(size_t)n * HH + cb * 128 + c] = Cs[r * LDC + c] + bs[c];
    }
}

// =====================================================================
// Fused edge kernel: GEMM1 (4 column passes) -> H in smem -> GEMM2 -> out + atomics
// grid 2500, 512 threads, 1 CTA/SM
// =====================================================================
__global__ __launch_bounds__(512, 1)
void edge_fused_kernel(const int* __restrict__ eidx, const float* __restrict__ b2,
                       float* __restrict__ out_e)
{
    extern __shared__ char smc[];
    __half* Hs = (__half*)(smc + OFF_H);
    float*  Cs = (float*)(smc + OFF_PC);
    float*  bs = (float*)(smc + FOFF_BIAS);
    int* ssend = (int*)(smc + FOFF_IDX);
    int* srecv = ssend + 128;

    const int tid = threadIdx.x;
    const int w = tid >> 5;
    const int m0 = (w >> 2) * 32, n0 = (w & 3) * 32;   // 4x4 warp grid, 32x32 tiles
    const int e0 = blockIdx.x * 128;

    if (tid < 128) {
        int s = eidx[e0 + tid];
        ssend[tid] = min(max(s, 0), NN - 1);
        bs[tid] = b2[tid];
    } else if (tid < 256) {
        int r = eidx[NE + e0 + tid - 128];
        srecv[tid - 128] = min(max(r, 0), NN - 1);
    }
    __syncthreads();

    // ---------------- Phase 1: H[:, cb*128..+128] per pass ----------------
    for (int cb = 0; cb < 4; cb++) {
        auto loadA = [&](int buf, int kc) {
            int row = tid >> 2, seg = tid & 3;
            cpa16h((__half*)(smc + FA_ST(buf)) + row * LDA_H + seg * 8,
                   g_eah + (size_t)(e0 + row) * DD + kc * 32 + seg * 8);
        };
        auto loadB = [&](int buf, int kc) {
            int row = tid >> 4, seg = tid & 15;
            cpa16h((__half*)(smc + FB_ST(buf)) + row * LDB_H + seg * 8,
                   g_W1h + (size_t)(256 + kc * 32 + row) * HH + cb * 128 + seg * 8);
        };

        FragC acc[2][2];
        #pragma unroll
        for (int i = 0; i < 2; i++)
            #pragma unroll
            for (int j = 0; j < 2; j++) wmma::fill_fragment(acc[i][j], 0.0f);

        loadA(0, 0); loadB(0, 0); cp_commit();
        loadA(1, 1); loadB(1, 1); cp_commit();
        for (int kc = 0; kc < 4; kc++) {
            if (kc < 3) cp_wait<1>(); else cp_wait<0>();
            __syncthreads();
            if (kc + 2 < 4) {
                int nb = (kc + 2) % NS;               // FIX: was (kc + 2) without modulo
                loadA(nb, kc + 2); loadB(nb, kc + 2); cp_commit();
            }
            int cur = kc % NS;
            mma_32x32((__half*)(smc + FA_ST(cur)), LDA_H,
                      (__half*)(smc + FB_ST(cur)), acc, m0, n0);
        }
        __syncthreads();

        #pragma unroll
        for (int i = 0; i < 2; i++)
            #pragma unroll
            for (int j = 0; j < 2; j++)
                wmma::store_matrix_sync(Cs + (m0 + i * 16) * LDC + n0 + j * 16,
                                        acc[i][j], LDC, wmma::mem_row_major);
        __syncthreads();

        // epilogue1: C + Z1[s] + Z2[r] -> relu -> half -> Hs
        for (int idx = tid; idx < 4096; idx += 512) {
            int r = idx >> 5, q = idx & 31;
            int c = q * 4;
            const float4 z1 = *(const float4*)(g_Z1 + (size_t)ssend[r] * HH + cb * 128 + c);
            const float4 z2 = *(const float4*)(g_Z2 + (size_t)srecv[r] * HH + cb * 128 + c);
            const float* cp = Cs + r * LDC + c;
            float v0 = cp[0] + z1.x + z2.x;
            float v1 = cp[1] + z1.y + z2.y;
            float v2 = cp[2] + z1.z + z2.z;
            float v3 = cp[3] + z1.w + z2.w;
            __half2* dst = (__half2*)(Hs + (size_t)r * LDH + cb * 128 + c);
            dst[0] = __floats2half2_rn(v0 > 0.0f ? v0 : 0.0f, v1 > 0.0f ? v1 : 0.0f);
            dst[1] = __floats2half2_rn(v2 > 0.0f ? v2 : 0.0f, v3 > 0.0f ? v3 : 0.0f);
        }
        __syncthreads();
    }

    // ---------------- Phase 2: out = H @ W2 + b2 ----------------
    {
        auto loadB2 = [&](int buf, int kc) {
            int row = tid >> 4, seg = tid & 15;
            cpa16h((__half*)(smc + FB_ST(buf)) + row * LDB_H + seg * 8,
                   g_W2h + (size_t)(kc * 32 + row) * DD + seg * 8);
        };

        FragC acc[2][2];
        #pragma unroll
        for (int i = 0; i < 2; i++)
            #pragma unroll
            for (int j = 0; j < 2; j++) wmma::fill_fragment(acc[i][j], 0.0f);

        loadB2(0, 0); cp_commit();
        loadB2(1, 1); cp_commit();
        for (int kc = 0; kc < 16; kc++) {
            if (kc < 15) cp_wait<1>(); else cp_wait<0>();
            __syncthreads();
            if (kc + 2 < 16) { loadB2((kc + 2) % NS, kc + 2); cp_commit(); }
            int cur = kc % NS;
            mma_32x32(Hs + kc * 32, LDH, (__half*)(smc + FB_ST(cur)), acc, m0, n0);
        }
        __syncthreads();

        #pragma unroll
        for (int i = 0; i < 2; i++)
            #pragma unroll
            for (int j = 0; j < 2; j++)
                wmma::store_matrix_sync(Cs + (m0 + i * 16) * LDC + n0 + j * 16,
                                        acc[i][j], LDC, wmma::mem_row_major);
        __syncthreads();

        for (int idx = tid; idx < 16384; idx += 512) {
            int r = idx >> 7, c = idx & 127;
            float v = Cs[r * LDC + c] + bs[c];
            out_e[(size_t)(e0 + r) * DD + c] = v;
            atomicAdd(&g_agg[(size_t)srecv[r] * DD + c], v);
        }
    }
}

// =====================================================================
// N1: g_Hn[n] = half(relu([xh|aggh] @ Wn1 + bn1)); grid (79, 4); K=256
// =====================================================================
__global__ __launch_bounds__(256, 2)
void n1_kernel(const float* __restrict__ b1)
{
    extern __shared__ char smc[];
    float* Cs = (float*)smc;
    float* bs = (float*)(smc + OFF_BIAS);

    const int tid = threadIdx.x;
    const int w = tid >> 5;
    const int m0 = (w >> 1) * 32, n0 = (w & 1) * 64;
    const int nb0 = blockIdx.x * 128;
    const int cb = blockIdx.y;

    if (tid < 128) bs[tid] = b1[cb * 128 + tid];
    __syncthreads();

    auto loadA = [&](int buf, int kc) {
        const int koff = (kc & 3) * 32;
        #pragma unroll
        for (int i = tid; i < 512; i += 256) {
            int row = i >> 2, seg = i & 3;
            int nr = min(nb0 + row, NN - 1);
            const __half* src = (kc < 4) ? (g_xh + (size_t)nr * DD + koff)
                                         : (g_aggh + (size_t)nr * DD + koff);
            cpa16h((__half*)(smc + OFF_A(buf)) + row * LDA_H + seg * 8, src + seg * 8);
        }
    };
    auto loadB = [&](int buf, int kc) {
        #pragma unroll
        for (int i = tid; i < 512; i += 256) {
            int row = i >> 4, seg = i & 15;
            cpa16h((__half*)(smc + OFF_B(buf)) + row * LDB_H + seg * 8,
                   g_Wn1h + (size_t)(kc * 32 + row) * HH + cb * 128 + seg * 8);
        }
    };

    FragC acc[2][4];
    #pragma unroll
    for (int i = 0; i < 2; i++)
        #pragma unroll
        for (int j = 0; j < 4; j++) wmma::fill_fragment(acc[i][j], 0.0f);

    GEMM_MAIN(8, loadA, loadB);
    STORE_C();

    for (int idx = tid; idx < 16384; idx += 256) {
        int r = idx >> 7, c = idx & 127;
        int n = nb0 + r;
        if (n < NN) {
            float v = Cs[r * LDC + c] + bs[c];
            g_Hn[(size_t)n * HH + cb * 128 + c] = __float2half(v > 0.0f ? v : 0.0f);
        }
    }
}

// =====================================================================
// N2: out_n = g_Hn @ Wn2 + bn2; self-cleans g_agg. grid 79; K=512
// =====================================================================
__global__ __launch_bounds__(256, 2)
void n2_kernel(const float* __restrict__ b2, float* __restrict__ out_n)
{
    extern __shared__ char smc[];
    float* Cs = (float*)smc;
    float* bs = (float*)(smc + OFF_BIAS);

    const int tid = threadIdx.x;
    const int w = tid >> 5;
    const int m0 = (w >> 1) * 32, n0 = (w & 1) * 64;
    const int nb0 = blockIdx.x * 128;

    if (tid < 128) bs[tid] = b2[tid];
    __syncthreads();

    auto loadA = [&](int buf, int kc) {
        #pragma unroll
        for (int i = tid; i < 512; i += 256) {
            int row = i >> 2, seg = i & 3;
            int nr = min(nb0 + row, NN - 1);
            cpa16h((__half*)(smc + OFF_A(buf)) + row * LDA_H + seg * 8,
                   g_Hn + (size_t)nr * HH + kc * 32 + seg * 8);
        }
    };
    auto loadB = [&](int buf, int kc) {
        #pragma unroll
        for (int i = tid; i < 512; i += 256) {
            int row = i >> 4, seg = i & 15;
            cpa16h((__half*)(smc + OFF_B(buf)) + row * LDB_H + seg * 8,
                   g_Wn2h + (size_t)(kc * 32 + row) * DD + seg * 8);
        }
    };

    FragC acc[2][4];
    #pragma unroll
    for (int i = 0; i < 2; i++)
        #pragma unroll
        for (int j = 0; j < 4; j++) wmma::fill_fragment(acc[i][j], 0.0f);

    GEMM_MAIN(16, loadA, loadB);
    STORE_C();

    for (int idx = tid; idx < 16384; idx += 256) {
        int r = idx >> 7, c = idx & 127;
        int n = nb0 + r;
        if (n < NN) {
            out_n[(size_t)n * DD + c] = Cs[r * LDC + c] + bs[c];
            g_agg[(size_t)n * DD + c] = 0.0f;
        }
    }
}

// ---------------- launch ----------------
extern "C" void kernel_launch(void* const* d_in, const int* in_sizes, int n_in,
                              void* d_out, int out_size)
{
    const float* x   = (const float*)d_in[0];
    const int*   ei  = (const int*)d_in[1];
    const float* ea  = (const float*)d_in[2];
    const float* We1 = (const float*)d_in[3];
    const float* be1 = (const float*)d_in[4];
    const float* We2 = (const float*)d_in[5];
    const float* be2 = (const float*)d_in[6];
    const float* Wn1 = (const float*)d_in[7];
    const float* bn1 = (const float*)d_in[8];
    const float* Wn2 = (const float*)d_in[9];
    const float* bn2 = (const float*)d_in[10];

    float* out_nodes = (float*)d_out;
    float* out_edges = out_nodes + (size_t)NN * DD;

    cudaFuncSetAttribute(z_kernel,          cudaFuncAttributeMaxDynamicSharedMemorySize, SMEM_BYTES);
    cudaFuncSetAttribute(edge_fused_kernel, cudaFuncAttributeMaxDynamicSharedMemorySize, FUSED_SMEM);
    cudaFuncSetAttribute(n1_kernel,         cudaFuncAttributeMaxDynamicSharedMemorySize, SMEM_BYTES);
    cudaFuncSetAttribute(n2_kernel,         cudaFuncAttributeMaxDynamicSharedMemorySize, SMEM_BYTES);

    prep_kernel<<<4096, 256>>>(x, ea, We1, We2, Wn1, Wn2);                 // 1
    z_kernel<<<dim3(79, 4, 2), 256, SMEM_BYTES>>>(be1);                    // 2
    dummy_kernel<<<1, 32>>>();                                             // 3
    edge_fused_kernel<<<NE / 128, 512, FUSED_SMEM>>>(ei, be2, out_edges);  // 4 <- ncu capture
    cvt_agg_kernel<<<1280, 256>>>();                                       // 5
    n1_kernel<<<dim3((NN + 127) / 128, 4), 256, SMEM_BYTES>>>(bn1);        // 6
    n2_kernel<<<(NN + 127) / 128, 256, SMEM_BYTES>>>(bn2, out_nodes);      // 7
}

// round 17
// speedup vs baseline: 1.1768x; 1.1768x over previous
#include <cuda_runtime.h>
#include <mma.h>
#include <cuda_fp16.h>
#include <cstdint>

using namespace nvcuda;

#define NN 10000
#define NE 320000
#define DD 128
#define HH 512

#define NX  (NN * DD)
#define NEA (NE * DD)

// ---------------- static device scratch ----------------
__device__ float  g_agg[NX];
__device__ __half g_aggh[NX];
__device__ __half g_xh[NX];
__device__ __half g_eah[NEA];
__device__ __half g_W1h[384 * 512];
__device__ __half g_W2h[512 * 128];
__device__ __half g_Wn1h[256 * 512];
__device__ __half g_Wn2h[512 * 128];
__device__ __half g_He[(size_t)NE * HH];   // edge hidden (half, 327MB)
__device__ __half g_Hn[NN * HH];           // node hidden
__device__ float  g_Z1[NN * HH];           // x @ We1[0:128] + b1
__device__ float  g_Z2[NN * HH];           // x @ We1[128:256]

// ---------------- helpers ----------------
__device__ __forceinline__ uint32_t smem_u32(const void* p) {
    uint32_t a;
    asm("{ .reg .u64 t; cvta.to.shared.u64 t, %1; cvt.u32.u64 %0, t; }" : "=r"(a) : "l"(p));
    return a;
}
__device__ __forceinline__ void cpa16h(__half* s, const __half* g) {
    asm volatile("cp.async.cg.shared.global [%0], [%1], 16;"
                 :: "r"(smem_u32(s)), "l"(g) : "memory");
}
__device__ __forceinline__ void cp_commit() {
    asm volatile("cp.async.commit_group;" ::: "memory");
}
template<int N> __device__ __forceinline__ void cp_wait() {
    asm volatile("cp.async.wait_group %0;" :: "n"(N) : "memory");
}

using FragA = wmma::fragment<wmma::matrix_a, 16, 16, 16, __half, wmma::row_major>;
using FragB = wmma::fragment<wmma::matrix_b, 16, 16, 16, __half, wmma::row_major>;
using FragC = wmma::fragment<wmma::accumulator, 16, 16, 16, float>;

#define LDA_H 40     // A row stride, halves (32 + 8)
#define LDB_H 136    // B row stride, halves (128 + 8)
#define LDC   132    // C row stride, floats
#define NS    3

// CTA 64x128, 8 warps in 2x4 grid, warp tile 32x32 -> acc[2][2] (32 regs)
__device__ __forceinline__ void mma_c(const __half* __restrict__ A,
                                      const __half* __restrict__ B,
                                      FragC (&acc)[2][2], int m0, int n0)
{
    #pragma unroll
    for (int s = 0; s < 2; s++) {
        FragA af[2];
        FragB bf[2];
        #pragma unroll
        for (int i = 0; i < 2; i++)
            wmma::load_matrix_sync(af[i], A + (m0 + i * 16) * LDA_H + s * 16, LDA_H);
        #pragma unroll
        for (int j = 0; j < 2; j++)
            wmma::load_matrix_sync(bf[j], B + (s * 16) * LDB_H + n0 + j * 16, LDB_H);
        #pragma unroll
        for (int i = 0; i < 2; i++)
            #pragma unroll
            for (int j = 0; j < 2; j++)
                wmma::mma_sync(acc[i][j], af[i], bf[j], acc[i][j]);
    }
}

// ---------------- smem layout (bytes), all GEMM kernels ----------------
#define ASZB 5120                         // 64 x 40 halves
#define BSZB 8704                         // 32 x 136 halves
#define OFF_A(s) ((s) * ASZB)
#define OFF_B(s) (NS * ASZB + (s) * BSZB) // pipe: 3*(5120+8704) = 41472
#define OFF_BIAS 41472                    // 128 floats
#define OFF_IDX  41984                    // 128+128 ints
#define SMEM_BYTES 43008                  // 43KB -> 4 CTAs/SM
// C overlay (64 x 132 fp32 = 33792B) reuses [0, 41472)

#define GEMM_MAIN(KC, LOADA, LOADB)                                          \
    {                                                                        \
        _Pragma("unroll")                                                    \
        for (int s = 0; s < NS - 1; s++) { LOADA(s, s); LOADB(s, s); cp_commit(); } \
        for (int kc = 0; kc < (KC); kc++) {                                  \
            if (kc < (KC) - 1) cp_wait<1>(); else cp_wait<0>();              \
            __syncthreads();                                                 \
            if (kc + NS - 1 < (KC)) {                                        \
                LOADA((kc + NS - 1) % NS, kc + NS - 1);                      \
                LOADB((kc + NS - 1) % NS, kc + NS - 1);                      \
                cp_commit();                                                 \
            }                                                                \
            int cur = kc % NS;                                               \
            mma_c((__half*)(smc + OFF_A(cur)), (__half*)(smc + OFF_B(cur)),  \
                  acc, m0, n0);                                              \
        }                                                                    \
        __syncthreads();                                                     \
    }

#define STORE_C()                                                            \
    {                                                                        \
        _Pragma("unroll")                                                    \
        for (int i = 0; i < 2; i++)                                          \
            _Pragma("unroll")                                                \
            for (int j = 0; j < 2; j++)                                      \
                wmma::store_matrix_sync(Cs + (m0 + i * 16) * LDC + n0 + j * 16, \
                                        acc[i][j], LDC, wmma::mem_row_major); \
        __syncthreads();                                                     \
    }

#define INIT_ACC()                                                           \
    FragC acc[2][2];                                                         \
    _Pragma("unroll")                                                        \
    for (int i = 0; i < 2; i++)                                              \
        _Pragma("unroll")                                                    \
        for (int j = 0; j < 2; j++) wmma::fill_fragment(acc[i][j], 0.0f);

// ---------------- aux kernels ----------------
__global__ void dummy_kernel() {}

__device__ __forceinline__ void cvt4(__half* dst, const float* src) {
    float4 v = *(const float4*)src;
    __half2* d = (__half2*)dst;
    d[0] = __floats2half2_rn(v.x, v.y);
    d[1] = __floats2half2_rn(v.z, v.w);
}

__global__ void prep_kernel(const float* __restrict__ x, const float* __restrict__ ea,
                            const float* __restrict__ We1, const float* __restrict__ We2,
                            const float* __restrict__ Wn1, const float* __restrict__ Wn2)
{
    const int total4 = (NX + NEA + 196608 + 65536 + 131072 + 65536) / 4;
    for (int i = blockIdx.x * blockDim.x + threadIdx.x; i < total4; i += gridDim.x * blockDim.x) {
        int k = i * 4;
        if (k < NX)     { cvt4(g_xh + k, x + k);     continue; }
        k -= NX;
        if (k < NEA)    { cvt4(g_eah + k, ea + k);   continue; }
        k -= NEA;
        if (k < 196608) { cvt4(g_W1h + k, We1 + k);  continue; }
        k -= 196608;
        if (k < 65536)  { cvt4(g_W2h + k, We2 + k);  continue; }
        k -= 65536;
        if (k < 131072) { cvt4(g_Wn1h + k, Wn1 + k); continue; }
        k -= 131072;
        cvt4(g_Wn2h + k, Wn2 + k);
    }
}

__global__ void cvt_agg_kernel() {
    for (int i = blockIdx.x * blockDim.x + threadIdx.x; i * 4 < NX; i += gridDim.x * blockDim.x) {
        float4 v = *(const float4*)(g_agg + i * 4);
        __half2* d = (__half2*)(g_aggh + i * 4);
        d[0] = __floats2half2_rn(v.x, v.y);
        d[1] = __floats2half2_rn(v.z, v.w);
    }
}

// =====================================================================
// Z: g_Z1 = x @ We1[0:128] + b1 ; g_Z2 = x @ We1[128:256]
// grid (157, 4, 2). CTA 64x128, K=128
// =====================================================================
__global__ __launch_bounds__(256, 4)
void z_kernel(const float* __restrict__ b1)
{
    extern __shared__ char smc[];
    float* Cs = (float*)smc;
    float* bs = (float*)(smc + OFF_BIAS);

    const int tid = threadIdx.x;
    const int w = tid >> 5;
    const int m0 = (w >> 2) * 32, n0 = (w & 3) * 32;
    const int nb0 = blockIdx.x * 64;
    const int cb  = blockIdx.y;
    const int zsel = blockIdx.z;

    if (tid < 128) bs[tid] = (zsel == 0) ? b1[cb * 128 + tid] : 0.0f;
    __syncthreads();

    auto loadA = [&](int buf, int kc) {
        int row = tid >> 2, seg = tid & 3;
        int nr = min(nb0 + row, NN - 1);
        cpa16h((__half*)(smc + OFF_A(buf)) + row * LDA_H + seg * 8,
               g_xh + (size_t)nr * DD + kc * 32 + seg * 8);
    };
    auto loadB = [&](int buf, int kc) {
        #pragma unroll
        for (int i = tid; i < 512; i += 256) {
            int row = i >> 4, seg = i & 15;
            cpa16h((__half*)(smc + OFF_B(buf)) + row * LDB_H + seg * 8,
                   g_W1h + (size_t)(zsel * 128 + kc * 32 + row) * HH + cb * 128 + seg * 8);
        }
    };

    INIT_ACC();
    GEMM_MAIN(4, loadA, loadB);
    STORE_C();

    float* dst = zsel == 0 ? g_Z1 : g_Z2;
    for (int idx = tid; idx < 8192; idx += 256) {
        int r = idx >> 7, c = idx & 127;
        int n = nb0 + r;
        if (n < NN)
            dst[(size_t)n * HH + cb * 128 + c] = Cs[r * LDC + c] + bs[c];
    }
}

// =====================================================================
// E1': g_He = half(relu(ea @ We1[256:384] + Z1[s] + Z2[r]))
// grid (5000, 4). CTA 64x128, K=128
// =====================================================================
__global__ __launch_bounds__(256, 4)
void e1p_kernel(const int* __restrict__ eidx)
{
    extern __shared__ char smc[];
    float* Cs = (float*)smc;
    int* ssend = (int*)(smc + OFF_IDX);
    int* srecv = ssend + 128;

    const int tid = threadIdx.x;
    const int w = tid >> 5;
    const int m0 = (w >> 2) * 32, n0 = (w & 3) * 32;
    const int e0 = blockIdx.x * 64;
    const int cb = blockIdx.y;

    if (tid < 64) {
        int s = eidx[e0 + tid];
        ssend[tid] = min(max(s, 0), NN - 1);
    } else if (tid < 128) {
        int r = eidx[NE + e0 + tid - 64];
        srecv[tid - 64] = min(max(r, 0), NN - 1);
    }
    __syncthreads();

    auto loadA = [&](int buf, int kc) {
        int row = tid >> 2, seg = tid & 3;
        cpa16h((__half*)(smc + OFF_A(buf)) + row * LDA_H + seg * 8,
               g_eah + (size_t)(e0 + row) * DD + kc * 32 + seg * 8);
    };
    auto loadB = [&](int buf, int kc) {
        #pragma unroll
        for (int i = tid; i < 512; i += 256) {
            int row = i >> 4, seg = i & 15;
            cpa16h((__half*)(smc + OFF_B(buf)) + row * LDB_H + seg * 8,
                   g_W1h + (size_t)(256 + kc * 32 + row) * HH + cb * 128 + seg * 8);
        }
    };

    INIT_ACC();
    GEMM_MAIN(4, loadA, loadB);
    STORE_C();

    // epilogue: + Z1[s] + Z2[r] -> relu -> half -> g_He
    for (int idx = tid; idx < 2048; idx += 256) {
        int r = idx >> 5, q = idx & 31;
        int c = q * 4;
        const float4 z1 = *(const float4*)(g_Z1 + (size_t)ssend[r] * HH + cb * 128 + c);
        const float4 z2 = *(const float4*)(g_Z2 + (size_t)srecv[r] * HH + cb * 128 + c);
        const float* cp = Cs + r * LDC + c;
        float v0 = cp[0] + z1.x + z2.x;
        float v1 = cp[1] + z1.y + z2.y;
        float v2 = cp[2] + z1.z + z2.z;
        float v3 = cp[3] + z1.w + z2.w;
        __half2* dst = (__half2*)(g_He + (size_t)(e0 + r) * HH + cb * 128 + c);
        dst[0] = __floats2half2_rn(v0 > 0.0f ? v0 : 0.0f, v1 > 0.0f ? v1 : 0.0f);
        dst[1] = __floats2half2_rn(v2 > 0.0f ? v2 : 0.0f, v3 > 0.0f ? v3 : 0.0f);
    }
}

// =====================================================================
// E2: out_e = g_He @ W2 + b2; atomic scatter. grid 5000. CTA 64x128, K=512
// =====================================================================
__global__ __launch_bounds__(256, 4)
void e2_kernel(const int* __restrict__ eidx, const float* __restrict__ b2,
               float* __restrict__ out_e)
{
    extern __shared__ char smc[];
    float* Cs = (float*)smc;
    float* bs = (float*)(smc + OFF_BIAS);
    int* srecv = (int*)(smc + OFF_IDX);

    const int tid = threadIdx.x;
    const int w = tid >> 5;
    const int m0 = (w >> 2) * 32, n0 = (w & 3) * 32;
    const int e0 = blockIdx.x * 64;

    if (tid < 64) {
        int r = eidx[NE + e0 + tid];
        srecv[tid] = min(max(r, 0), NN - 1);
    } else if (tid < 192) {
        bs[tid - 64] = b2[tid - 64];
    }
    __syncthreads();

    auto loadA = [&](int buf, int kc) {
        int row = tid >> 2, seg = tid & 3;
        cpa16h((__half*)(smc + OFF_A(buf)) + row * LDA_H + seg * 8,
               g_He + (size_t)(e0 + row) * HH + kc * 32 + seg * 8);
    };
    auto loadB = [&](int buf, int kc) {
        #pragma unroll
        for (int i = tid; i < 512; i += 256) {
            int row = i >> 4, seg = i & 15;
            cpa16h((__half*)(smc + OFF_B(buf)) + row * LDB_H + seg * 8,
                   g_W2h + (size_t)(kc * 32 + row) * DD + seg * 8);
        }
    };

    INIT_ACC();
    GEMM_MAIN(16, loadA, loadB);
    STORE_C();

    for (int idx = tid; idx < 8192; idx += 256) {
        int r = idx >> 7, c = idx & 127;
        float v = Cs[r * LDC + c] + bs[c];
        out_e[(size_t)(e0 + r) * DD + c] = v;
        atomicAdd(&g_agg[(size_t)srecv[r] * DD + c], v);
    }
}

// =====================================================================
// N1: g_Hn = half(relu([xh|aggh] @ Wn1 + bn1)); grid (157, 4). K=256
// =====================================================================
__global__ __launch_bounds__(256, 4)
void n1_kernel(const float* __restrict__ b1)
{
    extern __shared__ char smc[];
    float* Cs = (float*)smc;
    float* bs = (float*)(smc + OFF_BIAS);

    const int tid = threadIdx.x;
    const int w = tid >> 5;
    const int m0 = (w >> 2) * 32, n0 = (w & 3) * 32;
    const int nb0 = blockIdx.x * 64;
    const int cb = blockIdx.y;

    if (tid < 128) bs[tid] = b1[cb * 128 + tid];
    __syncthreads();

    auto loadA = [&](int buf, int kc) {
        const int koff = (kc & 3) * 32;
        int row = tid >> 2, seg = tid & 3;
        int nr = min(nb0 + row, NN - 1);
        const __half* src = (kc < 4) ? (g_xh + (size_t)nr * DD + koff)
                                     : (g_aggh + (size_t)nr * DD + koff);
        cpa16h((__half*)(smc + OFF_A(buf)) + row * LDA_H + seg * 8, src + seg * 8);
    };
    auto loadB = [&](int buf, int kc) {
        #pragma unroll
        for (int i = tid; i < 512; i += 256) {
            int row = i >> 4, seg = i & 15;
            cpa16h((__half*)(smc + OFF_B(buf)) + row * LDB_H + seg * 8,
                   g_Wn1h + (size_t)(kc * 32 + row) * HH + cb * 128 + seg * 8);
        }
    };

    INIT_ACC();
    GEMM_MAIN(8, loadA, loadB);
    STORE_C();

    for (int idx = tid; idx < 8192; idx += 256) {
        int r = idx >> 7, c = idx & 127;
        int n = nb0 + r;
        if (n < NN) {
            float v = Cs[r * LDC + c] + bs[c];
            g_Hn[(size_t)n * HH + cb * 128 + c] = __float2half(v > 0.0f ? v : 0.0f);
        }
    }
}

// =====================================================================
// N2: out_n = g_Hn @ Wn2 + bn2; self-cleans g_agg. grid 157. K=512
// =====================================================================
__global__ __launch_bounds__(256, 4)
void n2_kernel(const float* __restrict__ b2, float* __restrict__ out_n)
{
    extern __shared__ char smc[];
    float* Cs = (float*)smc;
    float* bs = (float*)(smc + OFF_BIAS);

    const int tid = threadIdx.x;
    const int w = tid >> 5;
    const int m0 = (w >> 2) * 32, n0 = (w & 3) * 32;
    const int nb0 = blockIdx.x * 64;

    if (tid < 128) bs[tid] = b2[tid];
    __syncthreads();

    auto loadA = [&](int buf, int kc) {
        int row = tid >> 2, seg = tid & 3;
        int nr = min(nb0 + row, NN - 1);
        cpa16h((__half*)(smc + OFF_A(buf)) + row * LDA_H + seg * 8,
               g_Hn + (size_t)nr * HH + kc * 32 + seg * 8);
    };
    auto loadB = [&](int buf, int kc) {
        #pragma unroll
        for (int i = tid; i < 512; i += 256) {
            int row = i >> 4, seg = i & 15;
            cpa16h((__half*)(smc + OFF_B(buf)) + row * LDB_H + seg * 8,
                   g_Wn2h + (size_t)(kc * 32 + row) * DD + seg * 8);
        }
    };

    INIT_ACC();
    GEMM_MAIN(16, loadA, loadB);
    STORE_C();

    for (int idx = tid; idx < 8192; idx += 256) {
        int r = idx >> 7, c = idx & 127;
        int n = nb0 + r;
        if (n < NN) {
            out_n[(size_t)n * DD + c] = Cs[r * LDC + c] + bs[c];
            g_agg[(size_t)n * DD + c] = 0.0f;
        }
    }
}

// ---------------- launch ----------------
extern "C" void kernel_launch(void* const* d_in, const int* in_sizes, int n_in,
                              void* d_out, int out_size)
{
    const float* x   = (const float*)d_in[0];
    const int*   ei  = (const int*)d_in[1];
    const float* ea  = (const float*)d_in[2];
    const float* We1 = (const float*)d_in[3];
    const float* be1 = (const float*)d_in[4];
    const float* We2 = (const float*)d_in[5];
    const float* be2 = (const float*)d_in[6];
    const float* Wn1 = (const float*)d_in[7];
    const float* bn1 = (const float*)d_in[8];
    const float* Wn2 = (const float*)d_in[9];
    const float* bn2 = (const float*)d_in[10];

    float* out_nodes = (float*)d_out;
    float* out_edges = out_nodes + (size_t)NN * DD;

    prep_kernel<<<4096, 256>>>(x, ea, We1, We2, Wn1, Wn2);                 // 1
    z_kernel<<<dim3(157, 4, 2), 256, SMEM_BYTES>>>(be1);                   // 2
    dummy_kernel<<<1, 32>>>();                                             // 3
    e1p_kernel<<<dim3(NE / 64, 4), 256, SMEM_BYTES>>>(ei);                 // 4 <- ncu capture
    e2_kernel<<<NE / 64, 256, SMEM_BYTES>>>(ei, be2, out_edges);           // 5
    cvt_agg_kernel<<<1280, 256>>>();                                       // 6
    n1_kernel<<<dim3(157, 4), 256, SMEM_BYTES>>>(bn1);                     // 7
    n2_kernel<<<157, 256, SMEM_BYTES>>>(bn2, out_nodes);                   // 8
}